// round 1
// baseline (speedup 1.0000x reference)
#include <cuda_runtime.h>
#include <math.h>
#include <stdint.h>

#define VOCAB   32000
#define EMBED   300
#define HIDDEN  1024
#define BATCH   64
#define SEQLEN  512
#define GDIM    4096   // 4*HIDDEN

#define NCTA    128    // persistent CTAs (<=148 SMs, all resident)
#define P2T     128    // threads per persistent CTA

// ---------------- device scratch (no allocations allowed) ----------------
__device__ float    g_xz[(size_t)SEQLEN * BATCH * GDIM];   // [t][b][g] fp32, 512MB
__device__ float    g_hbuf[2][HIDDEN * BATCH];             // transposed [j][b], double buffered
__device__ unsigned g_bar_count;
__device__ volatile unsigned g_bar_gen;

// ---------------- grid barrier (all NCTA CTAs resident) ------------------
__device__ __forceinline__ void grid_barrier() {
    __syncthreads();
    if (threadIdx.x == 0) {
        __threadfence();
        unsigned g = g_bar_gen;
        if (atomicAdd(&g_bar_count, 1u) == NCTA - 1u) {
            atomicExch(&g_bar_count, 0u);
            __threadfence();
            g_bar_gen = g + 1u;
        } else {
            while (g_bar_gen == g) { __nanosleep(64); }
        }
        __threadfence();
    }
    __syncthreads();
}

// =========================================================================
// Phase 1: xz[t][b][g] = emb[seq[b][t]] @ W + bias
// M = T*B = 32768 (m = t*64 + b), K = 300, N = 4096
// =========================================================================
__global__ void __launch_bounds__(256) xz_gemm_kernel(
    const float* __restrict__ emb, const float* __restrict__ W,
    const float* __restrict__ bias, const int* __restrict__ seq)
{
    __shared__ float As[32][64];   // [k][m]
    __shared__ float Bs[32][64];   // [k][n]
    __shared__ int   toks[64];

    const int tid = threadIdx.x;
    const int m0  = blockIdx.y * 64;
    const int n0  = blockIdx.x * 64;

    if (tid < 64) {
        int m = m0 + tid;
        toks[tid] = seq[(m & 63) * SEQLEN + (m >> 6)];
    }
    __syncthreads();

    const int tx4 = (tid & 15) * 4;
    const int ty4 = (tid >> 4) * 4;

    float acc[4][4];
    {
        float4 bv = *(const float4*)&bias[n0 + tx4];
        #pragma unroll
        for (int i = 0; i < 4; i++) {
            acc[i][0] = bv.x; acc[i][1] = bv.y; acc[i][2] = bv.z; acc[i][3] = bv.w;
        }
    }

    for (int k0 = 0; k0 < EMBED; k0 += 32) {
        // --- A tile (gathered embedding rows), stored transposed [k][m] ---
        #pragma unroll
        for (int pass = 0; pass < 2; pass++) {
            int r  = (tid >> 3) + pass * 32;   // row within tile
            int cc = (tid & 7) * 4;            // k within tile
            int kk = k0 + cc;
            float4 v = make_float4(0.f, 0.f, 0.f, 0.f);
            if (kk < EMBED)   // EMBED % 4 == 0, so kk<300 => kk+3<=299
                v = *(const float4*)&emb[(size_t)toks[r] * EMBED + kk];
            As[cc + 0][r] = v.x; As[cc + 1][r] = v.y;
            As[cc + 2][r] = v.z; As[cc + 3][r] = v.w;
        }
        // --- B tile [k][n] ---
        #pragma unroll
        for (int pass = 0; pass < 2; pass++) {
            int r  = (tid >> 4) + pass * 16;
            int e  = k0 + r;
            int cc = (tid & 15) * 4;
            float4 v = make_float4(0.f, 0.f, 0.f, 0.f);
            if (e < EMBED)
                v = *(const float4*)&W[(size_t)e * GDIM + n0 + cc];
            *(float4*)&Bs[r][cc] = v;
        }
        __syncthreads();

        #pragma unroll
        for (int kk = 0; kk < 32; kk++) {
            float4 a = *(const float4*)&As[kk][ty4];
            float4 b = *(const float4*)&Bs[kk][tx4];
            acc[0][0] += a.x*b.x; acc[0][1] += a.x*b.y; acc[0][2] += a.x*b.z; acc[0][3] += a.x*b.w;
            acc[1][0] += a.y*b.x; acc[1][1] += a.y*b.y; acc[1][2] += a.y*b.z; acc[1][3] += a.y*b.w;
            acc[2][0] += a.z*b.x; acc[2][1] += a.z*b.y; acc[2][2] += a.z*b.z; acc[2][3] += a.z*b.w;
            acc[3][0] += a.w*b.x; acc[3][1] += a.w*b.y; acc[3][2] += a.w*b.z; acc[3][3] += a.w*b.w;
        }
        __syncthreads();
    }

    #pragma unroll
    for (int i = 0; i < 4; i++) {
        float4 v = make_float4(acc[i][0], acc[i][1], acc[i][2], acc[i][3]);
        *(float4*)&g_xz[(size_t)(m0 + ty4 + i) * GDIM + n0 + tx4] = v;
    }
}

// =========================================================================
// Phase 2: persistent masked-LSTM scan.
// CTA `cta` owns hidden columns j0..j0+7 (x4 gates = 32 z columns).
// R slice (1024x32, 128KB) stays resident in SMEM for all 512 steps.
// h double-buffered in global, transposed [j][b]; c/h state in registers.
// =========================================================================
__global__ void __launch_bounds__(P2T, 1) lstm_kernel(
    const float* __restrict__ Rm,     // [1024][4096]
    const int*   __restrict__ seq,    // [64][512]
    float*       __restrict__ out)    // [64][1024]
{
    extern __shared__ float sm[];
    float* R_s = sm;                   // [1024][32]
    float* h_s = sm + 1024 * 32;       // [128][64] per k-tile
    float* z_s = h_s + 128 * 64;       // [64][36] (padded)

    const int tid = threadIdx.x;
    const int cta = blockIdx.x;
    const int j0  = cta * 8;

    // load persistent R slice: local col c -> gate = c>>3, jl = c&7
    for (int idx = tid; idx < 1024 * 32; idx += P2T) {
        int k = idx >> 5, c = idx & 31;
        int gcol = (c >> 3) * HIDDEN + j0 + (c & 7);
        R_s[idx] = Rm[(size_t)k * GDIM + gcol];
    }

    const int myb = tid >> 1;            // batch owned in gate phase
    const int jlb = (tid & 1) * 4;       // local-j base (0 or 4)

    // zero own slice of h buffer 0 (transposed layout [j][b])
    #pragma unroll
    for (int q = 0; q < 4; q++)
        g_hbuf[0][(j0 + jlb + q) * BATCH + myb] = 0.f;

    float h_reg[4] = {0.f, 0.f, 0.f, 0.f};
    float c_reg[4] = {0.f, 0.f, 0.f, 0.f};

    // GEMM thread mapping: tile 64(b) x 32(c); thread = 4b x 4c
    const int tx4 = (tid & 7) * 4;
    const int ty4 = (tid >> 3) * 4;
    const int xz_col = (tx4 >> 3) * HIDDEN + j0 + (tx4 & 7);  // 4 consecutive cols

    grid_barrier();   // h_buf[0] fully zeroed everywhere

    int p = 0;
    for (int t = 0; t < SEQLEN; t++) {
        const float* hb  = g_hbuf[p];
        const float* xzt = g_xz + (size_t)t * (BATCH * GDIM);

        float acc[4][4];
        #pragma unroll
        for (int i = 0; i < 4; i++) {
            float4 v = *(const float4*)&xzt[(size_t)(ty4 + i) * GDIM + xz_col];
            acc[i][0] = v.x; acc[i][1] = v.y; acc[i][2] = v.z; acc[i][3] = v.w;
        }

        for (int kt = 0; kt < 8; kt++) {
            // load h tile [128][64]; .cv to bypass (non-coherent) L1
            #pragma unroll
            for (int r = 0; r < 16; r++) {
                int li = r * P2T + tid;
                int k  = li >> 4;
                int b4 = (li & 15) * 4;
                float4 v = __ldcv((const float4*)&hb[(size_t)(kt * 128 + k) * BATCH + b4]);
                *(float4*)&h_s[k * 64 + b4] = v;
            }
            __syncthreads();

            const float* Rp = R_s + kt * 128 * 32;
            #pragma unroll 8
            for (int kk = 0; kk < 128; kk++) {
                float4 hv = *(const float4*)&h_s[kk * 64 + ty4];
                float4 rv = *(const float4*)&Rp[kk * 32 + tx4];
                acc[0][0] += hv.x*rv.x; acc[0][1] += hv.x*rv.y; acc[0][2] += hv.x*rv.z; acc[0][3] += hv.x*rv.w;
                acc[1][0] += hv.y*rv.x; acc[1][1] += hv.y*rv.y; acc[1][2] += hv.y*rv.z; acc[1][3] += hv.y*rv.w;
                acc[2][0] += hv.z*rv.x; acc[2][1] += hv.z*rv.y; acc[2][2] += hv.z*rv.z; acc[2][3] += hv.z*rv.w;
                acc[3][0] += hv.w*rv.x; acc[3][1] += hv.w*rv.y; acc[3][2] += hv.w*rv.z; acc[3][3] += hv.w*rv.w;
            }
            __syncthreads();
        }

        // park z tile in smem for the (b,j)-major gate phase
        #pragma unroll
        for (int i = 0; i < 4; i++)
            *(float4*)&z_s[(ty4 + i) * 36 + tx4] =
                make_float4(acc[i][0], acc[i][1], acc[i][2], acc[i][3]);
        __syncthreads();

        // gate phase: this thread owns (b = myb, j = j0+jlb..+3)
        bool msk = (seq[myb * SEQLEN + t] != 0);
        const float* zb = z_s + myb * 36;
        #pragma unroll
        for (int q = 0; q < 4; q++) {
            int jl = jlb + q;
            float zi = zb[jl];
            float zf = zb[8  + jl];
            float zg = zb[16 + jl];
            float zo = zb[24 + jl];
            float ig = 1.f / (1.f + expf(-zi));
            float fg = 1.f / (1.f + expf(-zf));
            float gg = tanhf(zg);
            float og = 1.f / (1.f + expf(-zo));
            float cn = fg * c_reg[q] + ig * gg;
            float hn = og * tanhf(cn);
            if (msk) { c_reg[q] = cn; h_reg[q] = hn; }
        }
        float* hbn = g_hbuf[p ^ 1];
        #pragma unroll
        for (int q = 0; q < 4; q++)
            hbn[(j0 + jlb + q) * BATCH + myb] = h_reg[q];

        p ^= 1;
        grid_barrier();
    }

    // final h -> d_out [b][1024]
    *(float4*)&out[myb * HIDDEN + j0 + jlb] =
        make_float4(h_reg[0], h_reg[1], h_reg[2], h_reg[3]);
}

// ---------------- launch ----------------
extern "C" void kernel_launch(void* const* d_in, const int* in_sizes, int n_in,
                              void* d_out, int out_size) {
    const float* emb  = nullptr;
    const float* W    = nullptr;
    const float* Rm   = nullptr;
    const float* bias = nullptr;
    const int*   seq  = nullptr;
    for (int i = 0; i < n_in; i++) {
        switch (in_sizes[i]) {
            case VOCAB * EMBED:     emb  = (const float*)d_in[i]; break;  // 9,600,000
            case EMBED * GDIM:      W    = (const float*)d_in[i]; break;  // 1,228,800
            case HIDDEN * GDIM:     Rm   = (const float*)d_in[i]; break;  // 4,194,304
            case GDIM:              bias = (const float*)d_in[i]; break;  // 4,096
            case BATCH * SEQLEN:    seq  = (const int*)d_in[i];   break;  // 32,768
        }
    }
    (void)out_size;

    const int smem2 = (1024 * 32 + 128 * 64 + 64 * 36) * (int)sizeof(float); // 173,056 B
    cudaFuncSetAttribute(lstm_kernel, cudaFuncAttributeMaxDynamicSharedMemorySize, smem2);

    dim3 g1(GDIM / 64, (SEQLEN * BATCH) / 64);   // (64, 512)
    xz_gemm_kernel<<<g1, 256>>>(emb, W, bias, seq);
    lstm_kernel<<<NCTA, P2T, smem2>>>(Rm, seq, (float*)d_out);
}